// round 6
// baseline (speedup 1.0000x reference)
#include <cuda_runtime.h>

#define WARPS 8
#define THREADS 256
#define NSTEP 10
#define XSTRIDE 48   // floats per padded row; 48 % 32 == 16 -> conflict-free LDS.64

typedef unsigned long long u64;

__device__ __forceinline__ float setgt1(float a) {
    float r;
    asm("set.gt.f32.f32 %0, %1, %2;" : "=f"(r) : "f"(a), "f"(1.0f));
    return r;
}
__device__ __forceinline__ u64 fma2(u64 a, u64 b, u64 c) {
    u64 d;
    asm("fma.rn.f32x2 %0, %1, %2, %3;" : "=l"(d) : "l"(a), "l"(b), "l"(c));
    return d;
}
// 2-source packed subtract: rt=2 on the fma pipe (vs rt=3 for 3-source fma2).
// fma(s,-1,m) == rn(m-s) == sub.rn -> bit-identical replacement.
__device__ __forceinline__ u64 sub2(u64 a, u64 b) {
    u64 d;
    asm("sub.rn.f32x2 %0, %1, %2;" : "=l"(d) : "l"(a), "l"(b));
    return d;
}
__device__ __forceinline__ u64 pack2(float lo, float hi) {
    u64 d;
    asm("mov.b64 %0, {%1, %2};" : "=l"(d) : "f"(lo), "f"(hi));
    return d;
}
__device__ __forceinline__ void unpack2(u64 v, float& lo, float& hi) {
    asm("mov.b64 {%0, %1}, %2;" : "=f"(lo), "=f"(hi) : "l"(v));
}

// One warp per sample, 32 element-pairs per lane, rr-outer / ch-inner (taps
// loaded once per rr). Conv fully packed in f32x2 (9 FFMA2 per pair-ch, mid
// taps hoisted per rr, duplicated weight pairs broadcast from smem). Membrane
// recurrence: 1 fma2 (rt3) + 1 sub2 (rt2) per step, t=0 peeled (m0 = c
// exactly). 10 channel-packed (out0,out1) accumulators.
__global__ void __launch_bounds__(THREADS, 4)
snn_kernel(const float* __restrict__ x, const float* __restrict__ convw,
           const float* __restrict__ convb, const float* __restrict__ fcw,
           const float* __restrict__ fcb, float* __restrict__ out, int nB)
{
    __shared__ __align__(16) float sx[WARPS][18 * XSTRIDE];
    __shared__ __align__(16) float sw01[4096];  // interleaved (w0_i, w1_i)
    __shared__ __align__(16) u64 scw2[8 * 10];  // per ch: 9 dup'd weight pairs + dup'd bias

    const int tid  = threadIdx.x;
    const int warp = tid >> 5;
    const int lane = tid & 31;
    const long long b = (long long)blockIdx.x * WARPS + warp;

    for (int i = tid; i < 2048; i += THREADS) {
        sw01[2 * i]     = fcw[i];
        sw01[2 * i + 1] = fcw[2048 + i];
    }
    if (tid < 80) {
        int ch = tid / 10, k = tid % 10;
        float v = (k < 9) ? convw[ch * 9 + k] : convb[ch];
        scw2[tid] = pack2(v, v);
    }

    float* sxw = sx[warp];
    #pragma unroll
    for (int i = lane; i < 18 * XSTRIDE; i += 32) sxw[i] = 0.0f;
    __syncwarp();

    if (b < nB) {
        const float4* xb = (const float4*)(x + b * 256);
        #pragma unroll
        for (int i = lane; i < 64; i += 32) {
            float4 v = xb[i];
            int p = i * 4;
            int y = p >> 4, xx = p & 15;
            float* d = &sxw[(y + 1) * XSTRIDE + xx + 1];
            d[0] = v.x; d[1] = v.y; d[2] = v.z; d[3] = v.w;
        }
    }
    __syncthreads();

    if (b < nB) {
        u64 A[NSTEP];
        #pragma unroll
        for (int t = 0; t < NSTEP; t++) A[t] = 0ull;

        const u64 BETA2 = 0x3F6666663F666666ull; // (0.9f, 0.9f)

        #pragma unroll 1
        for (int rr = 0; rr < 4; rr++) {
            const int q  = lane + 32 * rr;   // pair index in channel
            const int y  = q >> 3;
            const int x0 = (q & 7) * 2;
            const float* rp = sxw + y * XSTRIDE + x0;

            // 6 aligned tap pairs, register-resident across the channel loop
            const u64 p00 = *(const u64*)(rp);
            const u64 p01 = *(const u64*)(rp + 2);
            const u64 p10 = *(const u64*)(rp + XSTRIDE);
            const u64 p11 = *(const u64*)(rp + XSTRIDE + 2);
            const u64 p20 = *(const u64*)(rp + 2 * XSTRIDE);
            const u64 p21 = *(const u64*)(rp + 2 * XSTRIDE + 2);
            // middle-tap pairs (ch-invariant -> hoisted out of channel loop)
            float a0l, a0h, a1l, a1h, b0l, b0h, b1l, b1h, c0l, c0h, c1l, c1h;
            unpack2(p00, a0l, a0h); unpack2(p01, a1l, a1h);
            unpack2(p10, b0l, b0h); unpack2(p11, b1l, b1h);
            unpack2(p20, c0l, c0h); unpack2(p21, c1l, c1h);
            const u64 mid0 = pack2(a0h, a1l);
            const u64 mid1 = pack2(b0h, b1l);
            const u64 mid2 = pack2(c0h, c1l);

            const int qb = q * 2;            // flat even element within channel

            #pragma unroll 1
            for (int ch = 0; ch < 8; ch++) {
                const u64* cw = &scw2[ch * 10];   // broadcast LDS.64s
                u64 c2 = cw[9];                   // dup'd bias
                c2 = fma2(cw[0], p00,  c2);
                c2 = fma2(cw[1], mid0, c2);
                c2 = fma2(cw[2], p01,  c2);
                c2 = fma2(cw[3], p10,  c2);
                c2 = fma2(cw[4], mid1, c2);
                c2 = fma2(cw[5], p11,  c2);
                c2 = fma2(cw[6], p20,  c2);
                c2 = fma2(cw[7], mid2, c2);
                c2 = fma2(cw[8], p21,  c2);

                const int ib = ch * 256 + qb;
                const float4 wv = *(const float4*)&sw01[2 * ib];
                const u64 wlo = pack2(wv.x, wv.y);   // (w0_ib,   w1_ib)
                const u64 whi = pack2(wv.z, wv.w);   // (w0_ib+1, w1_ib+1)

                // t = 0 peeled: m = beta*0 + c - 0 = c exactly
                u64 m2 = c2;
                float ma, mb;
                unpack2(m2, ma, mb);
                float sa = setgt1(ma);
                float sb = setgt1(mb);
                u64 s2 = pack2(sa, sb);
                A[0] = fma2(pack2(sa, sa), wlo, A[0]);
                A[0] = fma2(pack2(sb, sb), whi, A[0]);

                #pragma unroll
                for (int t = 1; t < NSTEP; t++) {
                    m2 = fma2(BETA2, m2, c2);  // beta*m + c
                    m2 = sub2(m2, s2);         // - reset (prev spike), rt2
                    unpack2(m2, ma, mb);
                    sa = setgt1(ma);
                    sb = setgt1(mb);
                    s2 = pack2(sa, sb);
                    A[t] = fma2(pack2(sa, sa), wlo, A[t]);
                    A[t] = fma2(pack2(sb, sb), whi, A[t]);
                }
            }
        }

        // warp-reduce the 10 packed (out0, out1) partial sums
        float r0[NSTEP], r1[NSTEP];
        #pragma unroll
        for (int t = 0; t < NSTEP; t++) unpack2(A[t], r0[t], r1[t]);
        #pragma unroll
        for (int off = 16; off > 0; off >>= 1) {
            #pragma unroll
            for (int t = 0; t < NSTEP; t++) {
                r0[t] += __shfl_down_sync(0xffffffffu, r0[t], off);
                r1[t] += __shfl_down_sync(0xffffffffu, r1[t], off);
            }
        }

        if (lane == 0) {
            const float fb0 = fcb[0], fb1 = fcb[1];
            float m20 = 0.f, m21 = 0.f, s20 = 0.f, s21 = 0.f, o0 = 0.f, o1 = 0.f;
            #pragma unroll
            for (int t = 0; t < NSTEP; t++) {
                float c0 = r0[t] + fb0;
                float c1 = r1[t] + fb1;
                m20 = fmaf(0.9f, m20, c0) - s20;
                m21 = fmaf(0.9f, m21, c1) - s21;
                s20 = (m20 > 1.0f) ? 1.0f : 0.0f;
                s21 = (m21 > 1.0f) ? 1.0f : 0.0f;
                o0 += s20;
                o1 += s21;
            }
            out[b * 2 + 0] = o0;
            out[b * 2 + 1] = o1;
        }
    }
}

extern "C" void kernel_launch(void* const* d_in, const int* in_sizes, int n_in,
                              void* d_out, int out_size) {
    const float* x  = (const float*)d_in[0];
    const float* cw = (const float*)d_in[1];
    const float* cb = (const float*)d_in[2];
    const float* fw = (const float*)d_in[3];
    const float* fb = (const float*)d_in[4];
    float* out = (float*)d_out;

    const int nB = in_sizes[0] / 256;
    const int blocks = (nB + WARPS - 1) / WARPS;
    snn_kernel<<<blocks, THREADS>>>(x, cw, cb, fw, fb, out, nB);
}

// round 7
// speedup vs baseline: 1.0087x; 1.0087x over previous
#include <cuda_runtime.h>

#define WARPS 8
#define THREADS 256
#define NSTEP 10
#define XSTRIDE 48   // floats per padded row; 48 % 32 == 16 -> conflict-free LDS.64

__device__ __forceinline__ float setgt1(float a) {
    float r;
    asm("set.gt.f32.f32 %0, %1, %2;" : "=f"(r) : "f"(a), "f"(1.0f));
    return r;
}

// FULL-SCALAR version of the R5 winner. Same loop structure (rr-outer /
// ch-inner tap reuse), same op ORDER everywhere (conv fma sequence,
// fma-then-sub recurrence, acc order sa*w_even then sb*w_odd, warp
// reduction) -> bit-identical output to R5/R6. No f32x2: deletes all
// pack/unpack MOVs and wide-op dispatch cost; t-loop is 10 slim issue
// slots per pair-step (2 FSET alu + 8 fma-pipe). t=0 peeled exactly
// (m0 = c, s0-subtract = 0).
__global__ void __launch_bounds__(THREADS, 4)
snn_kernel(const float* __restrict__ x, const float* __restrict__ convw,
           const float* __restrict__ convb, const float* __restrict__ fcw,
           const float* __restrict__ fcb, float* __restrict__ out, int nB)
{
    __shared__ __align__(16) float sx[WARPS][18 * XSTRIDE];
    __shared__ __align__(16) float sw01[4096];    // interleaved (w0_i, w1_i)
    __shared__ __align__(16) float scw4[8 * 12];  // per ch: w0..w8, bias, pad, pad

    const int tid  = threadIdx.x;
    const int warp = tid >> 5;
    const int lane = tid & 31;
    const long long b = (long long)blockIdx.x * WARPS + warp;

    for (int i = tid; i < 2048; i += THREADS) {
        sw01[2 * i]     = fcw[i];
        sw01[2 * i + 1] = fcw[2048 + i];
    }
    if (tid < 96) {
        int ch = tid / 12, k = tid % 12;
        float v = 0.0f;
        if (k < 9)       v = convw[ch * 9 + k];
        else if (k == 9) v = convb[ch];
        scw4[tid] = v;
    }

    float* sxw = sx[warp];
    #pragma unroll
    for (int i = lane; i < 18 * XSTRIDE; i += 32) sxw[i] = 0.0f;
    __syncwarp();

    if (b < nB) {
        const float4* xb = (const float4*)(x + b * 256);
        #pragma unroll
        for (int i = lane; i < 64; i += 32) {
            float4 v = xb[i];
            int p = i * 4;
            int y = p >> 4, xx = p & 15;
            float* d = &sxw[(y + 1) * XSTRIDE + xx + 1];
            d[0] = v.x; d[1] = v.y; d[2] = v.z; d[3] = v.w;
        }
    }
    __syncthreads();

    if (b < nB) {
        // 10 time steps x 2 output channels, scalar accumulators
        float o0[NSTEP], o1[NSTEP];
        #pragma unroll
        for (int t = 0; t < NSTEP; t++) { o0[t] = 0.0f; o1[t] = 0.0f; }

        #pragma unroll 1
        for (int rr = 0; rr < 4; rr++) {
            const int q  = lane + 32 * rr;   // pair index in channel
            const int y  = q >> 3;
            const int x0 = (q & 7) * 2;
            const float* rp = sxw + y * XSTRIDE + x0;
            // taps register-resident across the whole channel loop
            const float2 t00 = *(const float2*)(rp);
            const float2 t01 = *(const float2*)(rp + 2);
            const float2 t10 = *(const float2*)(rp + XSTRIDE);
            const float2 t11 = *(const float2*)(rp + XSTRIDE + 2);
            const float2 t20 = *(const float2*)(rp + 2 * XSTRIDE);
            const float2 t21 = *(const float2*)(rp + 2 * XSTRIDE + 2);

            const int qb = q * 2;            // flat even element within channel

            #pragma unroll 1
            for (int ch = 0; ch < 8; ch++) {
                const float4* cw4 = (const float4*)&scw4[ch * 12];
                const float4 wA = cw4[0];   // w0 w1 w2 w3
                const float4 wB = cw4[1];   // w4 w5 w6 w7
                const float4 wC = cw4[2];   // w8 bias - -

                // scalar conv, op order identical to R1/R4/R5
                float ca = wC.y, cb = wC.y;
                ca = fmaf(wA.x, t00.x, ca);  cb = fmaf(wA.x, t00.y, cb);
                ca = fmaf(wA.y, t00.y, ca);  cb = fmaf(wA.y, t01.x, cb);
                ca = fmaf(wA.z, t01.x, ca);  cb = fmaf(wA.z, t01.y, cb);
                ca = fmaf(wA.w, t10.x, ca);  cb = fmaf(wA.w, t10.y, cb);
                ca = fmaf(wB.x, t10.y, ca);  cb = fmaf(wB.x, t11.x, cb);
                ca = fmaf(wB.y, t11.x, ca);  cb = fmaf(wB.y, t11.y, cb);
                ca = fmaf(wB.z, t20.x, ca);  cb = fmaf(wB.z, t20.y, cb);
                ca = fmaf(wB.w, t20.y, ca);  cb = fmaf(wB.w, t21.x, cb);
                ca = fmaf(wC.x, t21.x, ca);  cb = fmaf(wC.x, t21.y, cb);

                const int ib = ch * 256 + qb;
                // wv = (w0_even, w1_even, w0_odd, w1_odd), one LDS.128
                const float4 wv = *(const float4*)&sw01[2 * ib];

                // t = 0 peeled: m = 0.9*0 + c - 0 = c exactly
                float ma = ca, mb = cb;
                float sa = setgt1(ma);
                float sb = setgt1(mb);
                o0[0] = fmaf(sa, wv.x, o0[0]);
                o0[0] = fmaf(sb, wv.z, o0[0]);
                o1[0] = fmaf(sa, wv.y, o1[0]);
                o1[0] = fmaf(sb, wv.w, o1[0]);

                #pragma unroll
                for (int t = 1; t < NSTEP; t++) {
                    ma = fmaf(0.9f, ma, ca);   // beta*m + c   (FFMA)
                    mb = fmaf(0.9f, mb, cb);
                    ma = ma - sa;              // - reset      (FADD)
                    mb = mb - sb;
                    sa = setgt1(ma);           // spk = m > 1  (FSET, alu)
                    sb = setgt1(mb);
                    // acc order: even half then odd half, per accumulator --
                    // identical summation order to the packed kernels
                    o0[t] = fmaf(sa, wv.x, o0[t]);
                    o0[t] = fmaf(sb, wv.z, o0[t]);
                    o1[t] = fmaf(sa, wv.y, o1[t]);
                    o1[t] = fmaf(sb, wv.w, o1[t]);
                }
            }
        }

        // warp-reduce the 10 (out0, out1) partial sums
        #pragma unroll
        for (int off = 16; off > 0; off >>= 1) {
            #pragma unroll
            for (int t = 0; t < NSTEP; t++) {
                o0[t] += __shfl_down_sync(0xffffffffu, o0[t], off);
                o1[t] += __shfl_down_sync(0xffffffffu, o1[t], off);
            }
        }

        if (lane == 0) {
            const float fb0 = fcb[0], fb1 = fcb[1];
            float m20 = 0.f, m21 = 0.f, s20 = 0.f, s21 = 0.f, a0 = 0.f, a1 = 0.f;
            #pragma unroll
            for (int t = 0; t < NSTEP; t++) {
                float c0 = o0[t] + fb0;
                float c1 = o1[t] + fb1;
                m20 = fmaf(0.9f, m20, c0) - s20;
                m21 = fmaf(0.9f, m21, c1) - s21;
                s20 = (m20 > 1.0f) ? 1.0f : 0.0f;
                s21 = (m21 > 1.0f) ? 1.0f : 0.0f;
                a0 += s20;
                a1 += s21;
            }
            out[b * 2 + 0] = a0;
            out[b * 2 + 1] = a1;
        }
    }
}

extern "C" void kernel_launch(void* const* d_in, const int* in_sizes, int n_in,
                              void* d_out, int out_size) {
    const float* x  = (const float*)d_in[0];
    const float* cw = (const float*)d_in[1];
    const float* cb = (const float*)d_in[2];
    const float* fw = (const float*)d_in[3];
    const float* fb = (const float*)d_in[4];
    float* out = (float*)d_out;

    const int nB = in_sizes[0] / 256;
    const int blocks = (nB + WARPS - 1) / WARPS;
    snn_kernel<<<blocks, THREADS>>>(x, cw, cb, fw, fb, out, nB);
}